// round 16
// baseline (speedup 1.0000x reference)
#include <cuda_runtime.h>
#include <cstdint>

// FiniteWindowTopologicalAttention — tf32 mma.sync GEMMs + fp32 attention
//   K0 : round weights -> tf32 copies    (tiny)
//   K1 : qkv = x @ w_qkv                 (tf32 mma, warp tile 64x32, 12 warps/SM)
//   K2 : windowed attention              (fp32, 128 thr/window — R13 proven)
//   K3 : out = ao @ w_proj + b_proj      (tf32 mma)
//
// R16: GEMM warp tile 64x64 -> 64x32 (acc 128 -> 64 regs) + launch_bounds(128,3)
// -> 3 CTAs/SM = 12 warps/SM (was 8). K1 was latency-bound (tensor 53%, issue
// 21.5%, 2 warps/SMSP); more resident warps decouple the sync convoys.
// Attention reverted to the R13 shape (R15's 64-thr/2q variant lost occupancy
// and spilled: 288 -> 546us).

#define D_MODEL 256
#define NQKV    768
#define M_TOK   262144          // 4 * 256 * 256
#define NWIN    16384           // 4 * 64 * 64

// scratch (allocation-free rule: __device__ globals)
__device__ float g_qkv   [(size_t)M_TOK * NQKV];     // 768 MB
__device__ float g_ao    [(size_t)M_TOK * D_MODEL];  // 256 MB (tf32-rounded)
__device__ float g_wqkv_r [D_MODEL * NQKV];
__device__ float g_wproj_r[D_MODEL * D_MODEL];

// ---------------- helpers -----------------------------------------------------
__device__ __forceinline__ float tf32r(float x) {
    uint32_t r;
    asm("cvt.rna.tf32.f32 %0, %1;" : "=r"(r) : "f"(x));
    return __uint_as_float(r);
}
__device__ __forceinline__ uint32_t tf32u(uint32_t x) {
    uint32_t r;
    asm("cvt.rna.tf32.f32 %0, %1;" : "=r"(r) : "f"(__uint_as_float(x)));
    return r;
}
__device__ __forceinline__ void mma_tf32(float c[4], const uint32_t a[4],
                                         const uint32_t b[2]) {
    asm volatile(
        "mma.sync.aligned.m16n8k8.row.col.f32.tf32.tf32.f32 "
        "{%0,%1,%2,%3}, {%4,%5,%6,%7}, {%8,%9}, {%0,%1,%2,%3};"
        : "+f"(c[0]), "+f"(c[1]), "+f"(c[2]), "+f"(c[3])
        : "r"(a[0]), "r"(a[1]), "r"(a[2]), "r"(a[3]), "r"(b[0]), "r"(b[1]));
}
__device__ __forceinline__ void cp16(uint32_t dst, const void* src) {
    asm volatile("cp.async.cg.shared.global [%0], [%1], 16;"
                 :: "r"(dst), "l"(src));
}

// ---------------- pre-pass kernel ---------------------------------------------
__global__ void round_w_kernel(const float* __restrict__ in,
                               float* __restrict__ out, int n)
{
    int i = blockIdx.x * blockDim.x + threadIdx.x;
    if (i < n) out[i] = tf32r(in[i]);
}

// ---------------- tf32 GEMM: C[M,N] = A[M,256] * B[256,N] (+bias) ------------
// BM=128, BN=64, BK=32. 128 threads = 4 warps (2m x 2n), warp tile 64x32.
// 2-stage race-free cp.async pipeline (R13 structure).
// Smem pitches: A 36 floats, B 72 floats -> all fragment LDS conflict-free:
//   A frag bank = (4g+t) % 32 distinct; B frag bank = (8t+g) % 32 distinct.
#define XS_F (128 * 36)          // 4608 floats
#define WS_F (32 * 72)           // 2304 floats
#define STAGE_F (XS_F + WS_F)    // 6912 floats
#define GEMM_SMEM_BYTES (2 * STAGE_F * 4)   // 55296 B

template<bool ROUND_A>
__global__ __launch_bounds__(128, 3)
void tf32_gemm_kernel(const float* __restrict__ A, const float* __restrict__ B,
                      float* __restrict__ C, const float* __restrict__ bias,
                      int N)
{
    extern __shared__ float smem[];
    const uint32_t sbase = (uint32_t)__cvta_generic_to_shared(smem);

    const int tid  = threadIdx.x;
    const int warp = tid >> 5, lane = tid & 31;
    const int wm = warp >> 1, wn = warp & 1;       // 2 x 2 warp grid, 64x32 each
    const int g  = lane >> 2, t = lane & 3;

    const size_t rowbase = (size_t)blockIdx.y * 128;
    const int    colbase = blockIdx.x * 64;

    float acc[4][4][4];
#pragma unroll
    for (int i = 0; i < 4; i++)
#pragma unroll
        for (int j = 0; j < 4; j++)
#pragma unroll
            for (int r = 0; r < 4; r++) acc[i][j][r] = 0.f;

    // tile copy: A 128x32 floats (1024 x 16B, 8/thr), B 32x64 (512 x 16B, 4/thr)
    auto issue_tile = [&](int kt, int buf) {
        uint32_t su = sbase + (uint32_t)(buf * STAGE_F * 4);
#pragma unroll
        for (int i = 0; i < 8; i++) {
            int ch = tid + i * 128;
            int r  = ch >> 3, kg = ch & 7;
            cp16(su + (uint32_t)((r * 36 + kg * 4) * 4),
                 A + (rowbase + r) * 256 + kt * 32 + kg * 4);
        }
#pragma unroll
        for (int i = 0; i < 4; i++) {
            int ch = tid + i * 128;
            int r  = ch >> 4, c = (ch & 15) << 2;
            cp16(su + (uint32_t)((XS_F + r * 72 + c) * 4),
                 B + (size_t)(kt * 32 + r) * N + colbase + c);
        }
        asm volatile("cp.async.commit_group;");
    };

    issue_tile(0, 0);

    for (int kt = 0; kt < 8; kt++) {
        // only tile kt can be outstanding -> wait 0 makes it resident; the
        // barrier proves all warps finished reading the OTHER buffer before
        // the refill below touches it. (race-free: R11 lesson)
        asm volatile("cp.async.wait_group 0;");
        __syncthreads();

        if (kt < 7) issue_tile(kt + 1, (kt + 1) & 1);   // overlaps compute

        const uint32_t* xs = (const uint32_t*)(smem + (kt & 1) * STAGE_F);
        const uint32_t* ws = xs + XS_F;

#pragma unroll
        for (int k8 = 0; k8 < 4; k8++) {
            const int k0 = k8 * 8;
            uint32_t a[4][4];
#pragma unroll
            for (int i = 0; i < 4; i++) {
                const int r0 = wm * 64 + i * 16;
                a[i][0] = xs[(r0 + g)     * 36 + k0 + t];
                a[i][1] = xs[(r0 + g + 8) * 36 + k0 + t];
                a[i][2] = xs[(r0 + g)     * 36 + k0 + t + 4];
                a[i][3] = xs[(r0 + g + 8) * 36 + k0 + t + 4];
                if (ROUND_A) {
                    a[i][0] = tf32u(a[i][0]); a[i][1] = tf32u(a[i][1]);
                    a[i][2] = tf32u(a[i][2]); a[i][3] = tf32u(a[i][3]);
                }
            }
            uint32_t b[4][2];
#pragma unroll
            for (int j = 0; j < 4; j++) {
                const int c0 = wn * 32 + j * 8;
                b[j][0] = ws[(k0 + t)     * 72 + c0 + g];
                b[j][1] = ws[(k0 + t + 4) * 72 + c0 + g];
            }
#pragma unroll
            for (int i = 0; i < 4; i++)
#pragma unroll
                for (int j = 0; j < 4; j++) mma_tf32(acc[i][j], a[i], b[j]);
        }
    }

    // epilogue: c0,c1 -> (m, n..n+1); c2,c3 -> (m+8, n..n+1)
#pragma unroll
    for (int i = 0; i < 4; i++) {
        const size_t m0 = rowbase + wm * 64 + i * 16 + g;
#pragma unroll
        for (int j = 0; j < 4; j++) {
            const int n0 = colbase + wn * 32 + j * 8 + t * 2;
            float2 v0 = make_float2(acc[i][j][0], acc[i][j][1]);
            float2 v1 = make_float2(acc[i][j][2], acc[i][j][3]);
            if (bias) {
                float2 bb = *(const float2*)(bias + n0);
                v0.x += bb.x; v0.y += bb.y;
                v1.x += bb.x; v1.y += bb.y;
            }
            *(float2*)(C + m0 * N + n0)       = v0;
            *(float2*)(C + (m0 + 8) * N + n0) = v1;
        }
    }
}

// ---------------- Windowed attention (R13 proven: 128 thr, 1 window) ----------
__global__ __launch_bounds__(128)
void attn_kernel(const float* __restrict__ qkv,
                 const float* __restrict__ rpb_table,
                 float* __restrict__ ao)
{
    __shared__ float skv [16 * 512];   // [token][ k(256) | v(256) ]
    __shared__ float srpb[49 * 8];

    const int tid = threadIdx.x;
    const int wid = blockIdx.x;
    const int b   = wid >> 12;
    const int tb  = (wid >> 6) & 63;
    const int sb_ = wid & 63;
    const int base = b * 65536 + tb * 1024 + sb_ * 4;

    for (int i = tid; i < 392; i += 128) srpb[i] = rpb_table[i];

#pragma unroll
    for (int i = 0; i < 16; i++) {
        int f = tid + i * 128;
        int tok = f >> 7;
        int c = (f & 127) << 2;
        int row = base + (tok >> 2) * 256 + (tok & 3);
        *(float4*)&skv[tok * 512 + c] =
            *(const float4*)(qkv + (size_t)row * NQKV + 256 + c);
    }

    const int h  = tid >> 4;
    const int qi = tid & 15;
    const int qt = qi >> 2, qs = qi & 3;
    const int qrow = base + qt * 256 + qs;

    float4 qv[8];
    const float4* qp = (const float4*)(qkv + (size_t)qrow * NQKV + h * 32);
#pragma unroll
    for (int u = 0; u < 8; u++) qv[u] = qp[u];

    __syncthreads();

    const float scale = 0.17677669529663687f;   // 32^-0.5
    float sc[16];
#pragma unroll
    for (int j = 0; j < 16; j++) {
        const float4* kp = (const float4*)&skv[j * 512 + h * 32];
        float a = 0.f;
#pragma unroll
        for (int u = 0; u < 8; u++) {
            float4 kv = kp[u];
            a += qv[u].x * kv.x + qv[u].y * kv.y + qv[u].z * kv.z + qv[u].w * kv.w;
        }
        int kt = j >> 2, ks = j & 3;
        int ridx = (qt - kt + 3) * 7 + (qs - ks + 3);
        sc[j] = a * scale + srpb[ridx * 8 + h];
    }

    float m = sc[0];
#pragma unroll
    for (int j = 1; j < 16; j++) m = fmaxf(m, sc[j]);
    float s = 0.f;
#pragma unroll
    for (int j = 0; j < 16; j++) { sc[j] = __expf(sc[j] - m); s += sc[j]; }
    const float inv = 1.f / s;

    float4 o[8];
#pragma unroll
    for (int u = 0; u < 8; u++) o[u] = make_float4(0.f, 0.f, 0.f, 0.f);
#pragma unroll
    for (int j = 0; j < 16; j++) {
        float w = sc[j] * inv;
        const float4* vp = (const float4*)&skv[j * 512 + 256 + h * 32];
#pragma unroll
        for (int u = 0; u < 8; u++) {
            float4 vv = vp[u];
            o[u].x += w * vv.x; o[u].y += w * vv.y;
            o[u].z += w * vv.z; o[u].w += w * vv.w;
        }
    }

    // write tf32-rounded ao so K3 fragment loads need no cvt
    float4* op = (float4*)(ao + (size_t)qrow * D_MODEL + h * 32);
#pragma unroll
    for (int u = 0; u < 8; u++) {
        float4 v = o[u];
        v.x = tf32r(v.x); v.y = tf32r(v.y); v.z = tf32r(v.z); v.w = tf32r(v.w);
        op[u] = v;
    }
}

// ---------------- launch ------------------------------------------------------
extern "C" void kernel_launch(void* const* d_in, const int* in_sizes, int n_in,
                              void* d_out, int out_size)
{
    const float* x      = (const float*)d_in[0];   // (4,256,256,256)
    const float* w_qkv  = (const float*)d_in[1];   // (256,768)
    const float* w_proj = (const float*)d_in[2];   // (256,256)
    const float* b_proj = (const float*)d_in[3];   // (256,)
    const float* rpb    = (const float*)d_in[4];   // (49,8)
    float* out = (float*)d_out;

    float *qkv_p, *ao_p, *wq_p, *wp_p;
    cudaGetSymbolAddress((void**)&qkv_p, g_qkv);
    cudaGetSymbolAddress((void**)&ao_p,  g_ao);
    cudaGetSymbolAddress((void**)&wq_p,  g_wqkv_r);
    cudaGetSymbolAddress((void**)&wp_p,  g_wproj_r);

    cudaFuncSetAttribute(tf32_gemm_kernel<true>,
                         cudaFuncAttributeMaxDynamicSharedMemorySize,
                         GEMM_SMEM_BYTES);
    cudaFuncSetAttribute(tf32_gemm_kernel<false>,
                         cudaFuncAttributeMaxDynamicSharedMemorySize,
                         GEMM_SMEM_BYTES);

    // pre-round weights only (x is rounded in-fragment inside K1; ao is
    // rounded by the attention epilogue)
    round_w_kernel<<<(D_MODEL * NQKV) / 256, 256>>>(w_qkv, wq_p, D_MODEL * NQKV);
    round_w_kernel<<<(D_MODEL * D_MODEL) / 256, 256>>>(w_proj, wp_p,
                                                       D_MODEL * D_MODEL);

    // K1: qkv = x @ w_qkv  (A = raw x, rounded per-fragment)
    tf32_gemm_kernel<true><<<dim3(NQKV / 64, M_TOK / 128), 128,
                             GEMM_SMEM_BYTES>>>(x, wq_p, qkv_p, nullptr, NQKV);

    // K2: attention
    attn_kernel<<<NWIN, 128>>>(qkv_p, rpb, ao_p);

    // K3: out = ao @ w_proj + b_proj  (A = ao, already tf32)
    tf32_gemm_kernel<false><<<dim3(D_MODEL / 64, M_TOK / 128), 128,
                              GEMM_SMEM_BYTES>>>(ao_p, wp_p, out, b_proj,
                                                 D_MODEL);
}

// round 17
// speedup vs baseline: 1.5877x; 1.5877x over previous
#include <cuda_runtime.h>
#include <cstdint>

// FiniteWindowTopologicalAttention — tf32 mma.sync GEMMs + 2q-blocked attention
//   K0 : round weights -> tf32 copies    (tiny)
//   K1 : qkv = x @ w_qkv                 (tf32 mma 64x64 warp tile — R13 exact)
//   K2 : windowed attention              (2 windows/CTA, 2 q-rows/thread)
//   K3 : out = ao @ w_proj + b_proj      (tf32 mma — R13 exact)
//
// R17: GEMMs reverted to R13 (64x64/8-warp is the measured local optimum;
// both 64x32/12-warp and 2q/64-thread attn regressed). Attention is
// LSU-instruction-rate bound (L1 94%, crossbar floor 4096 cyc/window);
// 2q-blocking halves that. R15's version failed on 64-thr CTAs + register
// spills; this one uses 128-thr CTAs over 2 windows and reuses the qv
// registers as the o accumulators (disjoint liveness) to stay spill-free.

#define D_MODEL 256
#define NQKV    768
#define M_TOK   262144          // 4 * 256 * 256
#define NWIN    16384           // 4 * 64 * 64

// scratch (allocation-free rule: __device__ globals)
__device__ float g_qkv   [(size_t)M_TOK * NQKV];     // 768 MB
__device__ float g_ao    [(size_t)M_TOK * D_MODEL];  // 256 MB (tf32-rounded)
__device__ float g_wqkv_r [D_MODEL * NQKV];
__device__ float g_wproj_r[D_MODEL * D_MODEL];

// ---------------- helpers -----------------------------------------------------
__device__ __forceinline__ float tf32r(float x) {
    uint32_t r;
    asm("cvt.rna.tf32.f32 %0, %1;" : "=r"(r) : "f"(x));
    return __uint_as_float(r);
}
__device__ __forceinline__ uint32_t tf32u(uint32_t x) {
    uint32_t r;
    asm("cvt.rna.tf32.f32 %0, %1;" : "=r"(r) : "f"(__uint_as_float(x)));
    return r;
}
__device__ __forceinline__ void mma_tf32(float c[4], const uint32_t a[4],
                                         const uint32_t b[2]) {
    asm volatile(
        "mma.sync.aligned.m16n8k8.row.col.f32.tf32.tf32.f32 "
        "{%0,%1,%2,%3}, {%4,%5,%6,%7}, {%8,%9}, {%0,%1,%2,%3};"
        : "+f"(c[0]), "+f"(c[1]), "+f"(c[2]), "+f"(c[3])
        : "r"(a[0]), "r"(a[1]), "r"(a[2]), "r"(a[3]), "r"(b[0]), "r"(b[1]));
}
__device__ __forceinline__ void cp16(uint32_t dst, const void* src) {
    asm volatile("cp.async.cg.shared.global [%0], [%1], 16;"
                 :: "r"(dst), "l"(src));
}

// ---------------- pre-pass kernel ---------------------------------------------
__global__ void round_w_kernel(const float* __restrict__ in,
                               float* __restrict__ out, int n)
{
    int i = blockIdx.x * blockDim.x + threadIdx.x;
    if (i < n) out[i] = tf32r(in[i]);
}

// ---------------- tf32 GEMM (R13 exact): C = A[M,256] * B[256,N] (+bias) -----
// BM=128, BN=128, BK=32. 128 threads = 4 warps (2m x 2n), warp tile 64x64.
#define XS_F (128 * 36)          // 4608 floats
#define WS_F (32 * 136)          // 4352 floats
#define STAGE_F (XS_F + WS_F)    // 8960 floats
#define GEMM_SMEM_BYTES (2 * STAGE_F * 4)   // 71680 B

template<bool ROUND_A>
__global__ __launch_bounds__(128, 2)
void tf32_gemm_kernel(const float* __restrict__ A, const float* __restrict__ B,
                      float* __restrict__ C, const float* __restrict__ bias,
                      int N)
{
    extern __shared__ float smem[];
    const uint32_t sbase = (uint32_t)__cvta_generic_to_shared(smem);

    const int tid  = threadIdx.x;
    const int warp = tid >> 5, lane = tid & 31;
    const int wm = warp >> 1, wn = warp & 1;       // 2 x 2 warp grid, 64x64 each
    const int g  = lane >> 2, t = lane & 3;

    const size_t rowbase = (size_t)blockIdx.y * 128;
    const int    colbase = blockIdx.x * 128;

    float acc[4][8][4];
#pragma unroll
    for (int i = 0; i < 4; i++)
#pragma unroll
        for (int j = 0; j < 8; j++)
#pragma unroll
            for (int r = 0; r < 4; r++) acc[i][j][r] = 0.f;

    auto issue_tile = [&](int kt, int buf) {
        uint32_t su = sbase + (uint32_t)(buf * STAGE_F * 4);
#pragma unroll
        for (int i = 0; i < 8; i++) {
            int ch = tid + i * 128;
            int r  = ch >> 3, kg = ch & 7;
            cp16(su + (uint32_t)((r * 36 + kg * 4) * 4),
                 A + (rowbase + r) * 256 + kt * 32 + kg * 4);
        }
#pragma unroll
        for (int i = 0; i < 8; i++) {
            int ch = tid + i * 128;
            int r  = ch >> 5, c = (ch & 31) << 2;
            cp16(su + (uint32_t)((XS_F + r * 136 + c) * 4),
                 B + (size_t)(kt * 32 + r) * N + colbase + c);
        }
        asm volatile("cp.async.commit_group;");
    };

    issue_tile(0, 0);

    for (int kt = 0; kt < 8; kt++) {
        asm volatile("cp.async.wait_group 0;");
        __syncthreads();

        if (kt < 7) issue_tile(kt + 1, (kt + 1) & 1);   // overlaps compute

        const uint32_t* xs = (const uint32_t*)(smem + (kt & 1) * STAGE_F);
        const uint32_t* ws = xs + XS_F;

#pragma unroll
        for (int k8 = 0; k8 < 4; k8++) {
            const int k0 = k8 * 8;
            uint32_t a[4][4];
#pragma unroll
            for (int i = 0; i < 4; i++) {
                const int r0 = wm * 64 + i * 16;
                a[i][0] = xs[(r0 + g)     * 36 + k0 + t];
                a[i][1] = xs[(r0 + g + 8) * 36 + k0 + t];
                a[i][2] = xs[(r0 + g)     * 36 + k0 + t + 4];
                a[i][3] = xs[(r0 + g + 8) * 36 + k0 + t + 4];
                if (ROUND_A) {
                    a[i][0] = tf32u(a[i][0]); a[i][1] = tf32u(a[i][1]);
                    a[i][2] = tf32u(a[i][2]); a[i][3] = tf32u(a[i][3]);
                }
            }
            uint32_t b[8][2];
#pragma unroll
            for (int j = 0; j < 8; j++) {
                const int c0 = wn * 64 + j * 8;
                b[j][0] = ws[(k0 + t)     * 136 + c0 + g];
                b[j][1] = ws[(k0 + t + 4) * 136 + c0 + g];
            }
#pragma unroll
            for (int i = 0; i < 4; i++)
#pragma unroll
                for (int j = 0; j < 8; j++) mma_tf32(acc[i][j], a[i], b[j]);
        }
    }

#pragma unroll
    for (int i = 0; i < 4; i++) {
        const size_t m0 = rowbase + wm * 64 + i * 16 + g;
#pragma unroll
        for (int j = 0; j < 8; j++) {
            const int n0 = colbase + wn * 64 + j * 8 + t * 2;
            float2 v0 = make_float2(acc[i][j][0], acc[i][j][1]);
            float2 v1 = make_float2(acc[i][j][2], acc[i][j][3]);
            if (bias) {
                float2 bb = *(const float2*)(bias + n0);
                v0.x += bb.x; v0.y += bb.y;
                v1.x += bb.x; v1.y += bb.y;
            }
            *(float2*)(C + m0 * N + n0)       = v0;
            *(float2*)(C + (m0 + 8) * N + n0) = v1;
        }
    }
}

// ---------------- Windowed attention: 2 windows/CTA, 2 q-rows/thread ----------
// 128 threads: w2 = tid>>6 (window half), then 8 heads x 8 q-pairs.
// qi0 = 2*qp, qi1 = 2*qp+1 -> same qt, qs1 = qs0+1 -> consecutive global rows.
// Each K/V LDS.128 feeds two q-rows -> half the LDS instructions of R13.
// qv registers are reused as the o accumulators (disjoint liveness, no spill).
#define ATTN_SMEM_BYTES ((2 * 16 * 512 + 392) * 4)   // 66144 B

__global__ __launch_bounds__(128, 2)
void attn_kernel(const float* __restrict__ qkv,
                 const float* __restrict__ rpb_table,
                 float* __restrict__ ao)
{
    extern __shared__ float asmem[];
    float* skv  = asmem;                 // [2][16][512]
    float* srpb = asmem + 2 * 16 * 512;  // [49*8]

    const int tid = threadIdx.x;

    // window-pair bases
    const int wd0 = blockIdx.x * 2;
    const int wd1 = wd0 + 1;
    const int base0 = (wd0 >> 12) * 65536 + ((wd0 >> 6) & 63) * 1024 + (wd0 & 63) * 4;
    const int base1 = (wd1 >> 12) * 65536 + ((wd1 >> 6) & 63) * 1024 + (wd1 & 63) * 4;

    for (int i = tid; i < 392; i += 128) srpb[i] = rpb_table[i];

    // stage K,V for both windows: 4096 float4 chunks / 128 threads
#pragma unroll
    for (int i = 0; i < 32; i++) {
        int f = tid + i * 128;            // 0..4095
        int bse = (f & 2048) ? base1 : base0;
        int tok = (f >> 7) & 15;
        int c = (f & 127) << 2;
        int row = bse + (tok >> 2) * 256 + (tok & 3);
        *(float4*)&skv[(f >> 11) * 8192 + tok * 512 + c] =
            *(const float4*)(qkv + (size_t)row * NQKV + 256 + c);
    }

    const int w2 = tid >> 6;              // my window half
    const int t64 = tid & 63;
    const int h  = t64 >> 3;              // 0..7
    const int qp = t64 & 7;               // 0..7
    const int qt  = qp >> 1;
    const int qs0 = (qp & 1) * 2;         // 0 or 2
    const int mybase = w2 ? base1 : base0;
    const int qrow0 = mybase + qt * 256 + qs0;   // qrow1 = qrow0 + 1
    const float* mykv = skv + w2 * 8192;

    float4 qv0[8], qv1[8];
    {
        const float4* qp0 = (const float4*)(qkv + (size_t)qrow0 * NQKV + h * 32);
        const float4* qp1 = (const float4*)(qkv + (size_t)(qrow0 + 1) * NQKV + h * 32);
#pragma unroll
        for (int u = 0; u < 8; u++) { qv0[u] = qp0[u]; qv1[u] = qp1[u]; }
    }

    __syncthreads();

    const float scale = 0.17677669529663687f;   // 32^-0.5
    float sc0[16], sc1[16];
#pragma unroll
    for (int j = 0; j < 16; j++) {
        const float4* kp = (const float4*)&mykv[j * 512 + h * 32];
        float a0 = 0.f, a1 = 0.f;
#pragma unroll
        for (int u = 0; u < 8; u++) {
            float4 kv = kp[u];
            a0 += qv0[u].x * kv.x + qv0[u].y * kv.y + qv0[u].z * kv.z + qv0[u].w * kv.w;
            a1 += qv1[u].x * kv.x + qv1[u].y * kv.y + qv1[u].z * kv.z + qv1[u].w * kv.w;
        }
        int kt = j >> 2, ks = j & 3;
        int r0 = (qt - kt + 3) * 7 + (qs0 - ks + 3);
        sc0[j] = a0 * scale + srpb[r0 * 8 + h];
        sc1[j] = a1 * scale + srpb[(r0 + 1) * 8 + h];   // qs1 = qs0+1
    }

    float m0 = sc0[0], m1 = sc1[0];
#pragma unroll
    for (int j = 1; j < 16; j++) { m0 = fmaxf(m0, sc0[j]); m1 = fmaxf(m1, sc1[j]); }
    float s0 = 0.f, s1 = 0.f;
#pragma unroll
    for (int j = 0; j < 16; j++) {
        sc0[j] = __expf(sc0[j] - m0); s0 += sc0[j];
        sc1[j] = __expf(sc1[j] - m1); s1 += sc1[j];
    }
    const float inv0 = 1.f / s0, inv1 = 1.f / s1;

    // reuse qv0/qv1 as output accumulators (qv dead from here on)
#pragma unroll
    for (int u = 0; u < 8; u++) {
        qv0[u] = make_float4(0.f, 0.f, 0.f, 0.f);
        qv1[u] = make_float4(0.f, 0.f, 0.f, 0.f);
    }
#pragma unroll
    for (int j = 0; j < 16; j++) {
        float w0 = sc0[j] * inv0, w1 = sc1[j] * inv1;
        const float4* vp = (const float4*)&mykv[j * 512 + 256 + h * 32];
#pragma unroll
        for (int u = 0; u < 8; u++) {
            float4 vv = vp[u];
            qv0[u].x += w0 * vv.x; qv0[u].y += w0 * vv.y;
            qv0[u].z += w0 * vv.z; qv0[u].w += w0 * vv.w;
            qv1[u].x += w1 * vv.x; qv1[u].y += w1 * vv.y;
            qv1[u].z += w1 * vv.z; qv1[u].w += w1 * vv.w;
        }
    }

    // write tf32-rounded ao so K3 fragment loads need no cvt
    float4* op0 = (float4*)(ao + (size_t)qrow0 * D_MODEL + h * 32);
    float4* op1 = (float4*)(ao + (size_t)(qrow0 + 1) * D_MODEL + h * 32);
#pragma unroll
    for (int u = 0; u < 8; u++) {
        float4 v = qv0[u];
        v.x = tf32r(v.x); v.y = tf32r(v.y); v.z = tf32r(v.z); v.w = tf32r(v.w);
        op0[u] = v;
        v = qv1[u];
        v.x = tf32r(v.x); v.y = tf32r(v.y); v.z = tf32r(v.z); v.w = tf32r(v.w);
        op1[u] = v;
    }
}

// ---------------- launch ------------------------------------------------------
extern "C" void kernel_launch(void* const* d_in, const int* in_sizes, int n_in,
                              void* d_out, int out_size)
{
    const float* x      = (const float*)d_in[0];   // (4,256,256,256)
    const float* w_qkv  = (const float*)d_in[1];   // (256,768)
    const float* w_proj = (const float*)d_in[2];   // (256,256)
    const float* b_proj = (const float*)d_in[3];   // (256,)
    const float* rpb    = (const float*)d_in[4];   // (49,8)
    float* out = (float*)d_out;

    float *qkv_p, *ao_p, *wq_p, *wp_p;
    cudaGetSymbolAddress((void**)&qkv_p, g_qkv);
    cudaGetSymbolAddress((void**)&ao_p,  g_ao);
    cudaGetSymbolAddress((void**)&wq_p,  g_wqkv_r);
    cudaGetSymbolAddress((void**)&wp_p,  g_wproj_r);

    cudaFuncSetAttribute(tf32_gemm_kernel<true>,
                         cudaFuncAttributeMaxDynamicSharedMemorySize,
                         GEMM_SMEM_BYTES);
    cudaFuncSetAttribute(tf32_gemm_kernel<false>,
                         cudaFuncAttributeMaxDynamicSharedMemorySize,
                         GEMM_SMEM_BYTES);
    cudaFuncSetAttribute(attn_kernel,
                         cudaFuncAttributeMaxDynamicSharedMemorySize,
                         ATTN_SMEM_BYTES);

    // pre-round weights only (x is rounded in-fragment inside K1; ao is
    // rounded by the attention epilogue)
    round_w_kernel<<<(D_MODEL * NQKV) / 256, 256>>>(w_qkv, wq_p, D_MODEL * NQKV);
    round_w_kernel<<<(D_MODEL * D_MODEL) / 256, 256>>>(w_proj, wp_p,
                                                       D_MODEL * D_MODEL);

    // K1: qkv = x @ w_qkv  (A = raw x, rounded per-fragment)
    tf32_gemm_kernel<true><<<dim3(NQKV / 128, M_TOK / 128), 128,
                             GEMM_SMEM_BYTES>>>(x, wq_p, qkv_p, nullptr, NQKV);

    // K2: attention (2 windows per 128-thread CTA, 2 q-rows per thread)
    attn_kernel<<<NWIN / 2, 128, ATTN_SMEM_BYTES>>>(qkv_p, rpb, ao_p);

    // K3: out = ao @ w_proj + b_proj  (A = ao, already tf32)
    tf32_gemm_kernel<false><<<dim3(D_MODEL / 128, M_TOK / 128), 128,
                              GEMM_SMEM_BYTES>>>(ao_p, wp_p, out, b_proj,
                                                 D_MODEL);
}